// round 1
// baseline (speedup 1.0000x reference)
#include <cuda_runtime.h>
#include <cuda_bf16.h>

// out[i] = -((mean[i]-target[i])^2 / cov[i] + sum(log(cov)))
// output = [mean; cov] packed along dim 0: output[8192,2048], target[4096,2048].

__device__ double g_logdet;

__global__ void zero_accum_kernel() {
    g_logdet = 0.0;
}

// Pass 1: sum(log(cov)) over N floats (N = 8388608), float4 vectorized.
__global__ void logsum_kernel(const float* __restrict__ cov, int n4) {
    const float4* __restrict__ c4 = (const float4*)cov;
    float acc = 0.0f;
    int idx = blockIdx.x * blockDim.x + threadIdx.x;
    int stride = gridDim.x * blockDim.x;
    for (int i = idx; i < n4; i += stride) {
        float4 v = c4[i];
        acc += __logf(v.x) + __logf(v.y) + __logf(v.z) + __logf(v.w);
    }
    // warp reduce
    #pragma unroll
    for (int off = 16; off > 0; off >>= 1)
        acc += __shfl_xor_sync(0xFFFFFFFFu, acc, off);
    // block reduce via shared
    __shared__ float warp_sums[32];
    int lane = threadIdx.x & 31;
    int wid  = threadIdx.x >> 5;
    if (lane == 0) warp_sums[wid] = acc;
    __syncthreads();
    if (wid == 0) {
        int nwarps = (blockDim.x + 31) >> 5;
        float s = (lane < nwarps) ? warp_sums[lane] : 0.0f;
        #pragma unroll
        for (int off = 16; off > 0; off >>= 1)
            s += __shfl_xor_sync(0xFFFFFFFFu, s, off);
        if (lane == 0)
            atomicAdd(&g_logdet, (double)s);
    }
}

// Pass 2: out = -((mean - target)^2 / cov + logdet), float4 vectorized.
__global__ void nll_kernel(const float* __restrict__ mean,
                           const float* __restrict__ cov,
                           const float* __restrict__ target,
                           float* __restrict__ out, int n4) {
    float logdet = (float)g_logdet;
    const float4* __restrict__ m4 = (const float4*)mean;
    const float4* __restrict__ c4 = (const float4*)cov;
    const float4* __restrict__ t4 = (const float4*)target;
    float4* __restrict__ o4 = (float4*)out;
    int idx = blockIdx.x * blockDim.x + threadIdx.x;
    int stride = gridDim.x * blockDim.x;
    for (int i = idx; i < n4; i += stride) {
        float4 m = m4[i];
        float4 c = c4[i];
        float4 t = t4[i];
        float4 r;
        float dx = m.x - t.x;
        float dy = m.y - t.y;
        float dz = m.z - t.z;
        float dw = m.w - t.w;
        r.x = -(__fdividef(dx * dx, c.x) + logdet);
        r.y = -(__fdividef(dy * dy, c.y) + logdet);
        r.z = -(__fdividef(dz * dz, c.z) + logdet);
        r.w = -(__fdividef(dw * dw, c.w) + logdet);
        o4[i] = r;
    }
}

extern "C" void kernel_launch(void* const* d_in, const int* in_sizes, int n_in,
                              void* d_out, int out_size) {
    const float* output = (const float*)d_in[0];   // [8192, 2048]
    const float* target = (const float*)d_in[1];   // [4096, 2048]
    float* out = (float*)d_out;                    // [4096, 2048]

    const int n = out_size;            // 4096*2048 = 8388608
    const int n4 = n / 4;              // 2097152
    const float* mean = output;
    const float* cov  = output + n;

    zero_accum_kernel<<<1, 1>>>();

    // Reduction: grid-stride, enough blocks to saturate 148 SMs.
    logsum_kernel<<<148 * 8, 256>>>(cov, n4);

    // Elementwise: one float4 per thread.
    int blocks = (n4 + 255) / 256;     // 8192
    nll_kernel<<<blocks, 256>>>(mean, cov, target, out, n4);
}

// round 2
// speedup vs baseline: 1.2778x; 1.2778x over previous
#include <cuda_runtime.h>
#include <cuda_bf16.h>

// out[i] = -((mean[i]-target[i])^2 / cov[i] + sum(log(cov)))
// output = [mean; cov] packed along dim 0: output[8192,2048], target[4096,2048].

#define NBLOCKS 1184   // 148 SMs * 8
#define NTHREADS 256

__device__ float g_partials[NBLOCKS];

// Pass 1: per-block partial sums of log(cov). No atomics, no zeroing needed:
// every slot of g_partials is overwritten on every launch (deterministic).
__global__ void __launch_bounds__(NTHREADS) logsum_kernel(const float* __restrict__ cov, int n4) {
    const float4* __restrict__ c4 = (const float4*)cov;
    float acc = 0.0f;
    int idx = blockIdx.x * blockDim.x + threadIdx.x;
    int stride = gridDim.x * blockDim.x;
    for (int i = idx; i < n4; i += stride) {
        float4 v = c4[i];
        acc += __logf(v.x) + __logf(v.y) + __logf(v.z) + __logf(v.w);
    }
    // warp reduce
    #pragma unroll
    for (int off = 16; off > 0; off >>= 1)
        acc += __shfl_xor_sync(0xFFFFFFFFu, acc, off);
    __shared__ float warp_sums[NTHREADS / 32];
    int lane = threadIdx.x & 31;
    int wid  = threadIdx.x >> 5;
    if (lane == 0) warp_sums[wid] = acc;
    __syncthreads();
    if (wid == 0) {
        float s = (lane < (NTHREADS / 32)) ? warp_sums[lane] : 0.0f;
        #pragma unroll
        for (int off = 16; off > 0; off >>= 1)
            s += __shfl_xor_sync(0xFFFFFFFFu, s, off);
        if (lane == 0)
            g_partials[blockIdx.x] = s;
    }
}

// Pass 2: every block first reduces the 1184 partials (tiny, L2-resident),
// then does the elementwise epilogue. Streaming hints keep cov in L2:
//   mean/target -> __ldcs (evict-first), out -> __stcs, cov -> cached.
__global__ void __launch_bounds__(NTHREADS) nll_kernel(const float* __restrict__ mean,
                           const float* __restrict__ cov,
                           const float* __restrict__ target,
                           float* __restrict__ out, int n4) {
    // ---- reduce partials to a block-uniform logdet ----
    float s = 0.0f;
    for (int i = threadIdx.x; i < NBLOCKS; i += NTHREADS)
        s += g_partials[i];
    #pragma unroll
    for (int off = 16; off > 0; off >>= 1)
        s += __shfl_xor_sync(0xFFFFFFFFu, s, off);
    __shared__ float warp_sums[NTHREADS / 32];
    __shared__ float s_logdet;
    int lane = threadIdx.x & 31;
    int wid  = threadIdx.x >> 5;
    if (lane == 0) warp_sums[wid] = s;
    __syncthreads();
    if (threadIdx.x == 0) {
        float tot = 0.0f;
        #pragma unroll
        for (int w = 0; w < NTHREADS / 32; w++) tot += warp_sums[w];
        s_logdet = tot;
    }
    __syncthreads();
    const float logdet = s_logdet;

    // ---- elementwise main loop ----
    const float4* __restrict__ m4 = (const float4*)mean;
    const float4* __restrict__ c4 = (const float4*)cov;
    const float4* __restrict__ t4 = (const float4*)target;
    float4* __restrict__ o4 = (float4*)out;
    int idx = blockIdx.x * blockDim.x + threadIdx.x;
    int stride = gridDim.x * blockDim.x;
    for (int i = idx; i < n4; i += stride) {
        float4 m = __ldcs(&m4[i]);     // streaming: don't evict cov
        float4 t = __ldcs(&t4[i]);
        float4 c = c4[i];              // cached: should hit L2 from pass 1
        float4 r;
        float dx = m.x - t.x;
        float dy = m.y - t.y;
        float dz = m.z - t.z;
        float dw = m.w - t.w;
        r.x = -(__fdividef(dx * dx, c.x) + logdet);
        r.y = -(__fdividef(dy * dy, c.y) + logdet);
        r.z = -(__fdividef(dz * dz, c.z) + logdet);
        r.w = -(__fdividef(dw * dw, c.w) + logdet);
        __stcs(&o4[i], r);             // streaming store
    }
}

extern "C" void kernel_launch(void* const* d_in, const int* in_sizes, int n_in,
                              void* d_out, int out_size) {
    const float* output = (const float*)d_in[0];   // [8192, 2048]
    const float* target = (const float*)d_in[1];   // [4096, 2048]
    float* out = (float*)d_out;                    // [4096, 2048]

    const int n = out_size;            // 4096*2048 = 8388608
    const int n4 = n / 4;              // 2097152
    const float* mean = output;
    const float* cov  = output + n;

    logsum_kernel<<<NBLOCKS, NTHREADS>>>(cov, n4);
    nll_kernel<<<NBLOCKS, NTHREADS>>>(mean, cov, target, out, n4);
}